// round 17
// baseline (speedup 1.0000x reference)
#include <cuda_runtime.h>
#include <math.h>

#define B_    64
#define HID   1536
#define NH    12
#define NKV   2
#define HD    128
#define G_    6
#define INTER 8960
#define MAXB  256
#define BSZ   16
#define NBLK  16384
#define QSZ   1536
#define KVSZ  256
#define QKVN  2048
#define EPS_  1e-6f
#define SCALE 0.08838834764831845f   // 1/sqrt(128)
#define LOG2E 1.4426950408889634f
#define NVW   24                     // virtual (half-)warps per attention block
#define ATH   384                    // attention threads

typedef unsigned long long ull;

__device__ __forceinline__ void fma2(ull &d, ull a, ull b) {
    asm("fma.rn.f32x2 %0, %1, %2, %3;" : "=l"(d) : "l"(a), "l"(b), "l"(d));
}
__device__ __forceinline__ ull mul2(ull a, ull b) {
    ull r; asm("mul.rn.f32x2 %0, %1, %2;" : "=l"(r) : "l"(a), "l"(b)); return r;
}
__device__ __forceinline__ ull pack2(float x, float y) {
    ull r; asm("mov.b64 %0, {%1, %2};" : "=l"(r) : "f"(x), "f"(y)); return r;
}
__device__ __forceinline__ float2 unpack2(ull v) {
    float2 r; asm("mov.b64 {%0, %1}, %2;" : "=f"(r.x), "=f"(r.y) : "l"(v)); return r;
}

// ---------------- scratch (device globals; no allocation allowed) ----------
__device__ float g_res1[B_*HID];
__device__ float g_hn  [B_*HID];
__device__ float g_hn2 [B_*HID];
__device__ float g_qkv [B_*QKVN];
__device__ float g_attn[B_*QSZ];
__device__ float g_tmp [B_*HID];
__device__ float g_act [B_*INTER];
__device__ float g_part[2097152];    // split-K partials

// ---------------- fused add + RMSNorm -------------------------------------
__global__ void __launch_bounds__(256)
addnorm_kernel(const float* __restrict__ x, const float* __restrict__ y,
               const float* __restrict__ w,
               float* __restrict__ res, float* __restrict__ nout)
{
    int b = blockIdx.x, tid = threadIdx.x;
    const float* xr = x + b*HID;
    const float* yr = y + b*HID;
    float v[6];
    float ss = 0.f;
#pragma unroll
    for (int t = 0; t < 6; t++) {
        int i = tid + t*256;
        float s = xr[i] + yr[i];
        v[t] = s;
        ss += s*s;
    }
    __shared__ float red[8];
#pragma unroll
    for (int o = 16; o; o >>= 1) ss += __shfl_xor_sync(~0u, ss, o);
    if ((tid & 31) == 0) red[tid >> 5] = ss;
    __syncthreads();
    if (tid < 8) {
        float t2 = red[tid];
#pragma unroll
        for (int o = 4; o; o >>= 1) t2 += __shfl_xor_sync(0xffu, t2, o);
        if (tid == 0) red[0] = t2;
    }
    __syncthreads();
    float inv = rsqrtf(red[0] * (1.0f/HID) + EPS_);
#pragma unroll
    for (int t = 0; t < 6; t++) {
        int i = tid + t*256;
        res[b*HID + i]  = v[t];
        nout[b*HID + i] = v[t] * inv * w[i];
    }
}

// ---------------- SGEMM: C[64,N] = A[64,K] @ B[K,N] ------------------------
__global__ void __launch_bounds__(256)
gemm_f32(const float* __restrict__ A, const float* __restrict__ B,
         float* __restrict__ C, int K, int N, int klen)
{
    __shared__ __align__(16) float As[2][16][68];
    __shared__ __align__(16) float Bs[2][16][128];
    const int tid = threadIdx.x;
    const int n0 = blockIdx.x * 128;
    const int k0 = blockIdx.y * klen;
    float* Cp = C + (size_t)blockIdx.y * 64 * N;

    const int arow = tid >> 2, akq = (tid & 3) * 4;
    const int bk   = tid >> 5, bc  = (tid & 31) * 4;
    const int tr   = tid >> 4, tc  = tid & 15;

    const float* Aptr  = A + (size_t)arow*K + k0 + akq;
    const float* Bptr0 = B + (size_t)(k0 + bk)*N + n0 + bc;
    const float* Bptr1 = B + (size_t)(k0 + bk + 8)*N + n0 + bc;

    float4 av  = *(const float4*)Aptr;
    float4 b0v = *(const float4*)Bptr0;
    float4 b1v = *(const float4*)Bptr1;

    As[0][akq+0][arow] = av.x;
    As[0][akq+1][arow] = av.y;
    As[0][akq+2][arow] = av.z;
    As[0][akq+3][arow] = av.w;
    *(float4*)&Bs[0][bk  ][bc] = b0v;
    *(float4*)&Bs[0][bk+8][bc] = b1v;
    __syncthreads();

    float acc[4][8];
#pragma unroll
    for (int i = 0; i < 4; i++)
#pragma unroll
        for (int j = 0; j < 8; j++) acc[i][j] = 0.f;

    const int nk = klen >> 4;
    int buf = 0;
    for (int kt = 0; kt < nk; kt++) {
        float4 avn, b0n, b1n;
        if (kt + 1 < nk) {
            avn = *(const float4*)(Aptr + (kt+1)*16);
            b0n = *(const float4*)(Bptr0 + (size_t)(kt+1)*16*N);
            b1n = *(const float4*)(Bptr1 + (size_t)(kt+1)*16*N);
        }
#pragma unroll
        for (int kk = 0; kk < 16; kk++) {
            float4 a  = *(const float4*)&As[buf][kk][tr*4];
            float4 b0 = *(const float4*)&Bs[buf][kk][tc*8];
            float4 b1 = *(const float4*)&Bs[buf][kk][tc*8+4];
            acc[0][0] += a.x*b0.x; acc[0][1] += a.x*b0.y; acc[0][2] += a.x*b0.z; acc[0][3] += a.x*b0.w;
            acc[0][4] += a.x*b1.x; acc[0][5] += a.x*b1.y; acc[0][6] += a.x*b1.z; acc[0][7] += a.x*b1.w;
            acc[1][0] += a.y*b0.x; acc[1][1] += a.y*b0.y; acc[1][2] += a.y*b0.z; acc[1][3] += a.y*b0.w;
            acc[1][4] += a.y*b1.x; acc[1][5] += a.y*b1.y; acc[1][6] += a.y*b1.z; acc[1][7] += a.y*b1.w;
            acc[2][0] += a.z*b0.x; acc[2][1] += a.z*b0.y; acc[2][2] += a.z*b0.z; acc[2][3] += a.z*b0.w;
            acc[2][4] += a.z*b1.x; acc[2][5] += a.z*b1.y; acc[2][6] += a.z*b1.z; acc[2][7] += a.z*b1.w;
            acc[3][0] += a.w*b0.x; acc[3][1] += a.w*b0.y; acc[3][2] += a.w*b0.z; acc[3][3] += a.w*b0.w;
            acc[3][4] += a.w*b1.x; acc[3][5] += a.w*b1.y; acc[3][6] += a.w*b1.z; acc[3][7] += a.w*b1.w;
        }
        if (kt + 1 < nk) {
            int nb = buf ^ 1;
            As[nb][akq+0][arow] = avn.x;
            As[nb][akq+1][arow] = avn.y;
            As[nb][akq+2][arow] = avn.z;
            As[nb][akq+3][arow] = avn.w;
            *(float4*)&Bs[nb][bk  ][bc] = b0n;
            *(float4*)&Bs[nb][bk+8][bc] = b1n;
            __syncthreads();
            buf = nb;
        }
    }
#pragma unroll
    for (int r = 0; r < 4; r++) {
        float* crow = Cp + (size_t)(tr*4 + r)*N + n0 + tc*8;
        *(float4*)(crow)     = make_float4(acc[r][0], acc[r][1], acc[r][2], acc[r][3]);
        *(float4*)(crow + 4) = make_float4(acc[r][4], acc[r][5], acc[r][6], acc[r][7]);
    }
}

// ---------------- split-K reduce (+ optional bias) -------------------------
__global__ void __launch_bounds__(256)
reduce_kernel(const float* __restrict__ part, const float* __restrict__ bias,
              float* __restrict__ out, int MN, int N, int S)
{
    int i = blockIdx.x*256 + threadIdx.x;
    if (i >= MN) return;
    float s = bias ? bias[i % N] : 0.f;
    for (int p = 0; p < S; p++) s += part[(size_t)p*MN + i];
    out[i] = s;
}

// ---------------- fused qkv: split-K reduce + bias + NEOX RoPE -------------
__global__ void __launch_bounds__(256)
qkv_finish_kernel(const float* __restrict__ part, const float* __restrict__ bias,
                  const int* __restrict__ positions, float* __restrict__ qkv, int S)
{
    const int b = blockIdx.x, tid = threadIdx.x;
    const float pos = (float)positions[b];
    const int MN = B_*QKVN;
#pragma unroll
    for (int t = 0; t < 4; t++) {
        int p = tid + t*256;            // pair index 0..1023
        int chunk = p >> 6, d = p & 63;
        int c0 = chunk*128 + d;
        int c1 = c0 + 64;
        float s0 = bias[c0], s1 = bias[c1];
        for (int s = 0; s < S; s++) {
            const float* pp = part + (size_t)s*MN + b*QKVN;
            s0 += pp[c0];
            s1 += pp[c1];
        }
        if (chunk < NH + NKV) {
            float inv = exp2f((float)d * (-19.931568569324174f/64.0f)); // theta^-d/64
            float sn, cs;
            sincosf(pos * inv, &sn, &cs);
            float r0 = s0*cs - s1*sn;
            float r1 = s1*cs + s0*sn;
            s0 = r0; s1 = r1;
        }
        qkv[b*QKVN + c0] = s0;
        qkv[b*QKVN + c1] = s1;
    }
}

// ---------------- GQA paged decode attention -------------------------------
// block = (b, kv_head), 384 threads / 12 warps / 24 HALF-warp key lanes.
// Each half-warp (16 lanes x 8 dims = HD) owns one key per iteration:
// butterfly is only 4 rounds, and each warp amortizes the softmax update
// over 2 keys. exp2-domain softmax (log2e folded into q). Depth-2 prefetch
// ring. Invalid tail keys are neutralized branchlessly (s = -1e30 after the
// half-local reduction -> weight exactly 0). Cache never written.
__global__ void __launch_bounds__(ATH)
attn_kernel(const float* __restrict__ qkv, const float* __restrict__ kvc,
            const int* __restrict__ bt_all, const int* __restrict__ slot_map,
            const int* __restrict__ seq_lens, float* __restrict__ out)
{
    const int b    = blockIdx.x >> 1;
    const int kvh  = blockIdx.x & 1;
    const int warp = threadIdx.x >> 5;
    const int lane = threadIdx.x & 31;
    const int half = lane >> 4;
    const int l    = lane & 15;          // dim-lane: dims [l*8, l*8+8)
    const int vw   = warp*2 + half;      // 0..23
    const int len  = seq_lens[b];
    const int smap = slot_map[b];

    __shared__ int bts[MAXB];
    for (int i = threadIdx.x; i < MAXB; i += ATH) bts[i] = bt_all[b*MAXB + i];
    __syncthreads();

    const float* kc   = kvc;
    const float* vc   = kvc + (size_t)NBLK*BSZ*NKV*HD;
    const float* knew = qkv + b*QKVN + QSZ + kvh*HD;
    const float* vnew = qkv + b*QKVN + QSZ + KVSZ + kvh*HD;

    // q: 6 heads x 8 dims per lane, pre-scaled into exp2 domain
    float q[G_][8];
#pragma unroll
    for (int h = 0; h < G_; h++) {
        const float* qp = qkv + b*QKVN + (kvh*G_ + h)*HD + l*8;
        float4 qa = *(const float4*)qp;
        float4 qb = *(const float4*)(qp + 4);
        q[h][0]=qa.x*(SCALE*LOG2E); q[h][1]=qa.y*(SCALE*LOG2E);
        q[h][2]=qa.z*(SCALE*LOG2E); q[h][3]=qa.w*(SCALE*LOG2E);
        q[h][4]=qb.x*(SCALE*LOG2E); q[h][5]=qb.y*(SCALE*LOG2E);
        q[h][6]=qb.z*(SCALE*LOG2E); q[h][7]=qb.w*(SCALE*LOG2E);
    }

    float m[G_], lsum[G_];
    ull acc[G_][4];                     // 8 dims per lane as 4 f32x2
#pragma unroll
    for (int h = 0; h < G_; h++) {
        m[h] = -1e30f; lsum[h] = 0.f;
        acc[h][0] = acc[h][1] = acc[h][2] = acc[h][3] = 0ull;
    }

    // depth-2 prefetch ring (2 float4 each for k and v)
    float4 kb[2][2], vb[2][2];
#pragma unroll
    for (int st = 0; st < 2; st++) {
        int j = vw + st*NVW;
        int jc = (j < len) ? j : 0;
        int slot = bts[jc >> 4]*BSZ + (jc & 15);
        const float *kp, *vp;
        if (slot == smap) { kp = knew; vp = vnew; }
        else {
            size_t off = ((size_t)slot*NKV + kvh)*HD;
            kp = kc + off; vp = vc + off;
        }
        kb[st][0] = *(const float4*)(kp + l*8);
        kb[st][1] = *(const float4*)(kp + l*8 + 4);
        vb[st][0] = *(const float4*)(vp + l*8);
        vb[st][1] = *(const float4*)(vp + l*8 + 4);
    }

    int st = 0;
    for (int base = 0; base < len; base += NVW) {
        const int j = base + vw;
        const bool valid = (j < len);
        float4 k0 = kb[st][0], k1 = kb[st][1];
        float4 v0 = vb[st][0], v1 = vb[st][1];

        // prefetch 2 stages ahead into the slot we just consumed
        int jn = j + 2*NVW;
        if (jn < len) {
            int slot = bts[jn >> 4]*BSZ + (jn & 15);
            const float *kp, *vp;
            if (slot == smap) { kp = knew; vp = vnew; }
            else {
                size_t off = ((size_t)slot*NKV + kvh)*HD;
                kp = kc + off; vp = vc + off;
            }
            kb[st][0] = *(const float4*)(kp + l*8);
            kb[st][1] = *(const float4*)(kp + l*8 + 4);
            vb[st][0] = *(const float4*)(vp + l*8);
            vb[st][1] = *(const float4*)(vp + l*8 + 4);
        }
        st ^= 1;

        float s[G_];
#pragma unroll
        for (int h = 0; h < G_; h++)
            s[h] = q[h][0]*k0.x + q[h][1]*k0.y + q[h][2]*k0.z + q[h][3]*k0.w
                 + q[h][4]*k1.x + q[h][5]*k1.y + q[h][6]*k1.z + q[h][7]*k1.w;
        // 4-round butterfly within each 16-lane half (offsets < 16)
#pragma unroll
        for (int o = 8; o; o >>= 1) {
#pragma unroll
            for (int h = 0; h < G_; h++)
                s[h] += __shfl_xor_sync(~0u, s[h], o);
        }
#pragma unroll
        for (int h = 0; h < G_; h++)
            if (!valid) s[h] = -1e30f;   // -> p = 0 exactly (m already real)

        ull vq0 = pack2(v0.x, v0.y), vq1 = pack2(v0.z, v0.w);
        ull vq2 = pack2(v1.x, v1.y), vq3 = pack2(v1.z, v1.w);
#pragma unroll
        for (int h = 0; h < G_; h++) {
            float mn = fmaxf(m[h], s[h]);
            float p  = exp2f(s[h] - mn);
            float c  = exp2f(m[h] - mn);
            m[h]    = mn;
            lsum[h] = lsum[h]*c + p;
            ull p2 = pack2(p, p);
            ull c2 = pack2(c, c);
            acc[h][0] = mul2(acc[h][0], c2); fma2(acc[h][0], p2, vq0);
            acc[h][1] = mul2(acc[h][1], c2); fma2(acc[h][1], p2, vq1);
            acc[h][2] = mul2(acc[h][2], c2); fma2(acc[h][2], p2, vq2);
            acc[h][3] = mul2(acc[h][3], c2); fma2(acc[h][3], p2, vq3);
        }
    }

    // ---- merge 24 virtual warps: exp2 logsumexp weights + smem tree ----
    __shared__ float s_m[NVW][G_], s_l[NVW][G_], s_w[NVW][G_], s_L[G_];
    __shared__ float s_buf[12][G_][HD];   // 36 KB
    if (l == 0) {
#pragma unroll
        for (int h = 0; h < G_; h++) { s_m[vw][h] = m[h]; s_l[vw][h] = lsum[h]; }
    }
    __syncthreads();
    if (threadIdx.x < G_) {
        int h = threadIdx.x;
        float M = -1e30f;
#pragma unroll
        for (int w = 0; w < NVW; w++) M = fmaxf(M, s_m[w][h]);
        float L = 0.f;
#pragma unroll
        for (int w = 0; w < NVW; w++) {
            float wt = exp2f(s_m[w][h] - M);
            s_w[w][h] = wt;
            L += wt * s_l[w][h];
        }
        s_L[h] = 1.f / L;
    }
    __syncthreads();
    if (vw >= 12) {                        // warps 6..11
#pragma unroll
        for (int h = 0; h < G_; h++) {
            float wt = s_w[vw][h];
            float2 a0 = unpack2(acc[h][0]);
            float2 a1 = unpack2(acc[h][1]);
            float2 a2 = unpack2(acc[h][2]);
            float2 a3 = unpack2(acc[h][3]);
            float* dst = &s_buf[vw-12][h][l*8];
            dst[0] = wt*a0.x; dst[1] = wt*a0.y; dst[2] = wt*a1.x; dst[3] = wt*a1.y;
            dst[4] = wt*a2.x; dst[5] = wt*a2.y; dst[6] = wt*a3.x; dst[7] = wt*a3.y;
        }
    }
    __syncthreads();
    if (vw < 12) {                         // warps 0..5
#pragma unroll
        for (int h = 0; h < G_; h++) {
            float wt = s_w[vw][h];
            float2 a0 = unpack2(acc[h][0]);
            float2 a1 = unpack2(acc[h][1]);
            float2 a2 = unpack2(acc[h][2]);
            float2 a3 = unpack2(acc[h][3]);
            float* dst = &s_buf[vw][h][l*8];
            dst[0] += wt*a0.x; dst[1] += wt*a0.y; dst[2] += wt*a1.x; dst[3] += wt*a1.y;
            dst[4] += wt*a2.x; dst[5] += wt*a2.y; dst[6] += wt*a3.x; dst[7] += wt*a3.y;
        }
    }
    __syncthreads();
    // tree over 12 slots: +8 (slots 8-11), +4, +2, +1
    if (warp < 4) {
#pragma unroll
        for (int h = 0; h < G_; h++)
#pragma unroll
            for (int i = 0; i < 4; i++)
                s_buf[warp][h][lane*4+i] += s_buf[warp+8][h][lane*4+i];
    }
    __syncthreads();
    if (warp < 4) {
#pragma unroll
        for (int h = 0; h < G_; h++)
#pragma unroll
            for (int i = 0; i < 4; i++)
                s_buf[warp][h][lane*4+i] += s_buf[warp+4][h][lane*4+i];
    }
    __syncthreads();
    if (warp < 2) {
#pragma unroll
        for (int h = 0; h < G_; h++)
#pragma unroll
            for (int i = 0; i < 4; i++)
                s_buf[warp][h][lane*4+i] += s_buf[warp+2][h][lane*4+i];
    }
    __syncthreads();
    if (warp == 0) {
#pragma unroll
        for (int h = 0; h < G_; h++)
#pragma unroll
            for (int i = 0; i < 4; i++)
                s_buf[0][h][lane*4+i] += s_buf[1][h][lane*4+i];
    }
    __syncthreads();
    for (int idx = threadIdx.x; idx < G_*HD; idx += ATH) {
        int h = idx >> 7, d = idx & 127;
        out[b*QSZ + (kvh*G_ + h)*HD + d] = s_buf[0][h][d] * s_L[h];
    }
}

// ---------------- fused split-K reduce + SwiGLU for gate_up ---------------
__global__ void __launch_bounds__(256)
act_reduce_kernel(const float* __restrict__ part, float* __restrict__ out, int S)
{
    int i = blockIdx.x*256 + threadIdx.x;
    if (i >= B_*INTER) return;
    int b = i / INTER, c = i - b*INTER;
    size_t gi = (size_t)b*2*INTER + c;
    size_t ui = gi + INTER;
    float g = 0.f, u = 0.f;
    for (int p = 0; p < S; p++) {
        g += part[(size_t)p*B_*2*INTER + gi];
        u += part[(size_t)p*B_*2*INTER + ui];
    }
    out[i] = (g / (1.f + __expf(-g))) * u;
}

// ---------------- launch ----------------------------------------------------
extern "C" void kernel_launch(void* const* d_in, const int* in_sizes, int n_in,
                              void* d_out, int out_size)
{
    const int*   positions    = (const int*)  d_in[0];
    const float* hidden       = (const float*)d_in[1];
    const float* residual     = (const float*)d_in[2];
    const float* kv_cache     = (const float*)d_in[3];
    const int*   block_tables = (const int*)  d_in[4];
    const int*   slot_mapping = (const int*)  d_in[5];
    const int*   seq_lens     = (const int*)  d_in[6];
    // d_in[7] = is_prefill (statically 0)
    const float* w_qkv = (const float*)d_in[8];
    const float* b_qkv = (const float*)d_in[9];
    const float* w_o   = (const float*)d_in[10];
    const float* ln1   = (const float*)d_in[11];
    const float* ln2   = (const float*)d_in[12];
    const float* w_gu  = (const float*)d_in[13];
    const float* w_dn  = (const float*)d_in[14];
    float* out = (float*)d_out;   // [h (B*HID) | res2 (B*HID)]

    float *res1, *hn, *hn2, *qkv, *attn, *tmp, *act, *part;
    cudaGetSymbolAddress((void**)&res1, g_res1);
    cudaGetSymbolAddress((void**)&hn,   g_hn);
    cudaGetSymbolAddress((void**)&hn2,  g_hn2);
    cudaGetSymbolAddress((void**)&qkv,  g_qkv);
    cudaGetSymbolAddress((void**)&attn, g_attn);
    cudaGetSymbolAddress((void**)&tmp,  g_tmp);
    cudaGetSymbolAddress((void**)&act,  g_act);
    cudaGetSymbolAddress((void**)&part, g_part);

    // 1. res1 = hidden + residual ; hn = rmsnorm(res1)*ln1
    addnorm_kernel<<<B_, 256>>>(hidden, residual, ln1, res1, hn);

    // 2. qkv GEMM (split-K 8: 16x8 = 128 blocks, klen 192)
    gemm_f32<<<dim3(QKVN/128, 8), 256>>>(hn, w_qkv, part, HID, QKVN, 192);

    // 3. fused reduce + bias + RoPE
    qkv_finish_kernel<<<B_, 256>>>(part, b_qkv, positions, qkv, 8);

    // 4. paged GQA decode attention (half-warp-per-key)
    attn_kernel<<<B_*NKV, ATH>>>(qkv, kv_cache, block_tables, slot_mapping,
                                 seq_lens, attn);

    // 5. o-proj (split-K 12: 12x12 = 144 blocks, klen 128)
    gemm_f32<<<dim3(HID/128, 12), 256>>>(attn, w_o, part, QSZ, HID, 128);
    reduce_kernel<<<(B_*HID + 255)/256, 256>>>(part, nullptr, tmp, B_*HID, HID, 12);

    // 6. res2 = o + res1 (-> out second half) ; hn2 = rmsnorm(res2)*ln2
    addnorm_kernel<<<B_, 256>>>(tmp, res1, ln2, out + B_*HID, hn2);

    // 7. gate_up GEMM (140 blocks, no split) + fused SwiGLU
    gemm_f32<<<dim3(2*INTER/128, 1), 256>>>(hn2, w_gu, part, HID, 2*INTER, HID);
    act_reduce_kernel<<<(B_*INTER + 255)/256, 256>>>(part, act, 1);

    // 8. down GEMM (split-K 14: 12x14 = 168 blocks, klen 640) -> out first half
    gemm_f32<<<dim3(HID/128, 14), 256>>>(act, w_dn, part, INTER, HID, 640);
    reduce_kernel<<<(B_*HID + 255)/256, 256>>>(part, nullptr, out, B_*HID, HID, 14);
}